// round 4
// baseline (speedup 1.0000x reference)
#include <cuda_runtime.h>

// UnifiedQuantumRegressor — fused 3-layer MLP + global reduction, f32x2 edition.
//
// Algebraic fact (verified R1, rel_err 4e-7): all graph edge weights are 1.0 so
// mean_w == 1.0 exactly and attn == q_out; the O(N^2) fidelity stage is dead.
// out = (sum_i tanh(relu(relu(s_i@W1+b1)@W2+b2)@Wq+bq)) @ Wh + bh   (scalar)
//
// This round: packed fma.rn.f32x2 (2 MACs/lane/issue, PTX-only on Blackwell),
// warp-private rows (no block syncs in mainloop), fused deterministic final
// reduce (last-done block, fixed-order summation).

#define NTHREADS 256
#define TM       16          // rows per block = 2 per warp * 8 warps
#define NBLK     512         // 8192 / TM

__device__ float        g_partials[NBLK];
__device__ unsigned int g_count;     // zero-init; reset by last block each launch

__device__ __forceinline__ unsigned long long packf2(float lo, float hi) {
    unsigned long long r;
    asm("mov.b64 %0, {%1, %2};" : "=l"(r) : "f"(lo), "f"(hi));
    return r;
}
__device__ __forceinline__ void ffma2(unsigned long long& acc,
                                      unsigned long long a, unsigned long long b) {
    asm("fma.rn.f32x2 %0, %1, %2, %0;" : "+l"(acc) : "l"(a), "l"(b));
}
__device__ __forceinline__ float2 unpackf2(unsigned long long v) {
    float2 f;
    asm("mov.b64 {%0, %1}, %2;" : "=f"(f.x), "=f"(f.y) : "l"(v));
    return f;
}

__global__ __launch_bounds__(NTHREADS) void fused_mlp_kernel(
    const float* __restrict__ S,   // [8192,512]
    const float* __restrict__ W1,  // [512,256]
    const float* __restrict__ b1,  // [256]
    const float* __restrict__ W2,  // [256,256]
    const float* __restrict__ b2,  // [256]
    const float* __restrict__ Wq,  // [256,64]
    const float* __restrict__ bq,  // [64]
    const float* __restrict__ Wh,  // [64]
    const float* __restrict__ bh,  // [1]
    float* __restrict__ out)
{
    __shared__ float sE1[8][2][256];   // 16KB: enc1, per-warp slices
    __shared__ float sE2[8][2][256];   // 16KB: enc2, per-warp slices
    __shared__ float sRed[8];
    __shared__ int   sIsLast;

    const int tid  = threadIdx.x;
    const int w    = tid >> 5;
    const int lane = tid & 31;
    const int c8   = lane * 8;          // this thread's 8 output cols (stages 1-2)

    const float* s0p = S + (size_t)(blockIdx.x * TM + 2 * w) * 512;
    const float* s1p = s0p + 512;

    // ================= stage 1: enc1 = relu(S @ W1 + b1) =================
    {
        unsigned long long acc[2][4];
        #pragma unroll
        for (int r = 0; r < 2; ++r)
            #pragma unroll
            for (int j = 0; j < 4; ++j) acc[r][j] = 0ull;   // bits of (0.f,0.f)

        #pragma unroll 4
        for (int k = 0; k < 512; ++k) {
            const unsigned long long sp0 = packf2(s0p[k], s0p[k]);  // LDG broadcast
            const unsigned long long sp1 = packf2(s1p[k], s1p[k]);
            const ulonglong2 wa = *(const ulonglong2*)(W1 + k * 256 + c8);
            const ulonglong2 wb = *(const ulonglong2*)(W1 + k * 256 + c8 + 4);
            ffma2(acc[0][0], sp0, wa.x); ffma2(acc[0][1], sp0, wa.y);
            ffma2(acc[0][2], sp0, wb.x); ffma2(acc[0][3], sp0, wb.y);
            ffma2(acc[1][0], sp1, wa.x); ffma2(acc[1][1], sp1, wa.y);
            ffma2(acc[1][2], sp1, wb.x); ffma2(acc[1][3], sp1, wb.y);
        }
        const float4 bA = *(const float4*)(b1 + c8);
        const float4 bB = *(const float4*)(b1 + c8 + 4);
        #pragma unroll
        for (int r = 0; r < 2; ++r) {
            float2 p0 = unpackf2(acc[r][0]), p1 = unpackf2(acc[r][1]);
            float2 p2 = unpackf2(acc[r][2]), p3 = unpackf2(acc[r][3]);
            float4 v0, v1;
            v0.x = fmaxf(p0.x + bA.x, 0.f); v0.y = fmaxf(p0.y + bA.y, 0.f);
            v0.z = fmaxf(p1.x + bA.z, 0.f); v0.w = fmaxf(p1.y + bA.w, 0.f);
            v1.x = fmaxf(p2.x + bB.x, 0.f); v1.y = fmaxf(p2.y + bB.y, 0.f);
            v1.z = fmaxf(p3.x + bB.z, 0.f); v1.w = fmaxf(p3.y + bB.w, 0.f);
            *(float4*)(&sE1[w][r][c8])     = v0;
            *(float4*)(&sE1[w][r][c8 + 4]) = v1;
        }
    }
    __syncwarp();

    // ================= stage 2: enc2 = relu(enc1 @ W2 + b2) =================
    {
        unsigned long long acc[2][4];
        #pragma unroll
        for (int r = 0; r < 2; ++r)
            #pragma unroll
            for (int j = 0; j < 4; ++j) acc[r][j] = 0ull;

        #pragma unroll 4
        for (int k = 0; k < 256; ++k) {
            const unsigned long long sp0 = packf2(sE1[w][0][k], sE1[w][0][k]);  // LDS bcast
            const unsigned long long sp1 = packf2(sE1[w][1][k], sE1[w][1][k]);
            const ulonglong2 wa = *(const ulonglong2*)(W2 + k * 256 + c8);
            const ulonglong2 wb = *(const ulonglong2*)(W2 + k * 256 + c8 + 4);
            ffma2(acc[0][0], sp0, wa.x); ffma2(acc[0][1], sp0, wa.y);
            ffma2(acc[0][2], sp0, wb.x); ffma2(acc[0][3], sp0, wb.y);
            ffma2(acc[1][0], sp1, wa.x); ffma2(acc[1][1], sp1, wa.y);
            ffma2(acc[1][2], sp1, wb.x); ffma2(acc[1][3], sp1, wb.y);
        }
        const float4 bA = *(const float4*)(b2 + c8);
        const float4 bB = *(const float4*)(b2 + c8 + 4);
        #pragma unroll
        for (int r = 0; r < 2; ++r) {
            float2 p0 = unpackf2(acc[r][0]), p1 = unpackf2(acc[r][1]);
            float2 p2 = unpackf2(acc[r][2]), p3 = unpackf2(acc[r][3]);
            float4 v0, v1;
            v0.x = fmaxf(p0.x + bA.x, 0.f); v0.y = fmaxf(p0.y + bA.y, 0.f);
            v0.z = fmaxf(p1.x + bA.z, 0.f); v0.w = fmaxf(p1.y + bA.w, 0.f);
            v1.x = fmaxf(p2.x + bB.x, 0.f); v1.y = fmaxf(p2.y + bB.y, 0.f);
            v1.z = fmaxf(p3.x + bB.z, 0.f); v1.w = fmaxf(p3.y + bB.w, 0.f);
            *(float4*)(&sE2[w][r][c8])     = v0;
            *(float4*)(&sE2[w][r][c8 + 4]) = v1;
        }
    }
    __syncwarp();

    // ========= stage 3: q = tanh(enc2 @ Wq + bq);  p = q . Wh (partial) =========
    float p;
    {
        const int c2 = lane * 2;                       // 2 cols per lane (64 total)
        unsigned long long acc3[2] = {0ull, 0ull};
        #pragma unroll 4
        for (int k = 0; k < 256; ++k) {
            const unsigned long long wq = *(const unsigned long long*)(Wq + k * 64 + c2);
            ffma2(acc3[0], packf2(sE2[w][0][k], sE2[w][0][k]), wq);
            ffma2(acc3[1], packf2(sE2[w][1][k], sE2[w][1][k]), wq);
        }
        const float2 bq2 = *(const float2*)(bq + c2);
        const float2 wh2 = *(const float2*)(Wh + c2);
        const float2 q0 = unpackf2(acc3[0]);
        const float2 q1 = unpackf2(acc3[1]);
        p = tanhf(q0.x + bq2.x) * wh2.x + tanhf(q0.y + bq2.y) * wh2.y
          + tanhf(q1.x + bq2.x) * wh2.x + tanhf(q1.y + bq2.y) * wh2.y;
    }

    // ---- warp reduce, then block reduce (fixed order) ----
    #pragma unroll
    for (int o = 16; o > 0; o >>= 1)
        p += __shfl_down_sync(0xffffffffu, p, o);
    if (lane == 0) sRed[w] = p;
    __syncthreads();

    if (tid == 0) {
        float tot = 0.f;
        #pragma unroll
        for (int i = 0; i < 8; ++i) tot += sRed[i];
        g_partials[blockIdx.x] = tot;
        __threadfence();
        unsigned int c = atomicAdd(&g_count, 1u);
        sIsLast = (c == NBLK - 1u);
    }
    __syncthreads();

    // ---- last-done block performs the deterministic final reduction ----
    if (sIsLast) {
        volatile float* gp = g_partials;
        float v = gp[tid] + gp[tid + 256];
        #pragma unroll
        for (int o = 16; o > 0; o >>= 1)
            v += __shfl_down_sync(0xffffffffu, v, o);
        if (lane == 0) sRed[w] = v;
        __syncthreads();
        if (tid == 0) {
            float t = 0.f;
            #pragma unroll
            for (int i = 0; i < 8; ++i) t += sRed[i];
            out[0] = t + bh[0];
            g_count = 0;                 // self-reset for next graph replay
        }
    }
}

extern "C" void kernel_launch(void* const* d_in, const int* in_sizes, int n_in,
                              void* d_out, int out_size)
{
    const float* S  = (const float*)d_in[0];
    const float* W1 = (const float*)d_in[1];
    const float* b1 = (const float*)d_in[2];
    const float* W2 = (const float*)d_in[3];
    const float* b2 = (const float*)d_in[4];
    const float* Wq = (const float*)d_in[5];
    const float* bq = (const float*)d_in[6];
    const float* Wh = (const float*)d_in[7];
    const float* bh = (const float*)d_in[8];
    float* out = (float*)d_out;

    fused_mlp_kernel<<<NBLK, NTHREADS>>>(S, W1, b1, W2, b2, Wq, bq, Wh, bh, out);
}

// round 6
// speedup vs baseline: 2.8514x; 2.8514x over previous
#include <cuda_runtime.h>

// UnifiedQuantumRegressor — fused 3-layer MLP + reduction, f32x2 row-pair edition.
//
// Algebra (verified R1, rel_err 4e-7): all edge weights are 1.0 -> mean_w == 1.0
// exactly -> attn == q_out; the O(N^2) fidelity stage is dead.
// out = (sum_i tanh(relu(relu(s_i@W1+b1)@W2+b2)@Wq+bq)) @ Wh + bh
//
// f32x2 halves = ROW PAIRS. Activations live in smem as float2 (row2p,row2p+1)
// keyed by k; one broadcast LDS.128 feeds 4 row-pairs (1 L1 wavefront).
// Weights: one contiguous-lane LDG.128 per k (4 wavefronts) + 4 dup-movs.
// Per warp-k: 16 FFMA2 vs 6 wavefronts -> FMA-pipe bound (budget wf<=8).

#define NTHREADS 256
#define TM       32
#define NBLK     256          // 8192 / 32
#define PITCH    18           // float2 per smem row: 16 pairs + pad (keeps 16B align)

__device__ float        g_partials[NBLK];
__device__ unsigned int g_count;

typedef unsigned long long ull;

static __device__ __forceinline__ ull packf2(float lo, float hi) {
    ull r; asm("mov.b64 %0, {%1, %2};" : "=l"(r) : "f"(lo), "f"(hi)); return r;
}
static __device__ __forceinline__ void ffma2(ull& acc, ull a, ull b) {
    asm("fma.rn.f32x2 %0, %1, %2, %0;" : "+l"(acc) : "l"(a), "l"(b));
}
static __device__ __forceinline__ float2 unpackf2(ull v) {
    float2 f; asm("mov.b64 {%0, %1}, %2;" : "=f"(f.x), "=f"(f.y) : "l"(v)); return f;
}

__global__ __launch_bounds__(NTHREADS) void fused_mlp_kernel(
    const float* __restrict__ S,   // [8192,512]
    const float* __restrict__ W1,  // [512,256]
    const float* __restrict__ b1,  // [256]
    const float* __restrict__ W2,  // [256,256]
    const float* __restrict__ b2,  // [256]
    const float* __restrict__ Wq,  // [256,64]
    const float* __restrict__ bq,  // [64]
    const float* __restrict__ Wh,  // [64]
    const float* __restrict__ bh,  // [1]
    float* __restrict__ out)
{
    extern __shared__ unsigned char dynsm[];
    // sE1: [256][PITCH] pairs of enc1 (k-major)           36864 B
    // sE2: [256][PITCH] pairs of enc2 (k-major)           36864 B, overlays sS
    // sS : [128][PITCH] pairs of S chunk (k-major)        18432 B (dead before sE2 is born)
    float2 (*sE1)[PITCH] = (float2(*)[PITCH])(dynsm);
    float2 (*sE2)[PITCH] = (float2(*)[PITCH])(dynsm + 256 * PITCH * sizeof(float2));
    float2 (*sS )[PITCH] = (float2(*)[PITCH])(dynsm + 256 * PITCH * sizeof(float2));
    __shared__ float sRed[8];
    __shared__ int   sIsLast;

    const int tid  = threadIdx.x;
    const int w    = tid >> 5;
    const int lane = tid & 31;
    const int row0 = blockIdx.x * TM;

    // compute-tile mapping (stages 1 & 2): 8 rows x 4 cols per thread
    const int rg = tid >> 6;          // 0..3  -> pairs p0 = rg*4 .. rg*4+3 (rows rg*8..rg*8+7)
    const int cg = tid & 63;          // cols c0 = cg*4 .. cg*4+3
    const int p0 = rg * 4;
    const int c0 = cg * 4;

    // chunk-loader mapping: pair pr (0..15), k-quad kq (0..15)
    const int pr = tid >> 4;
    const int kq = tid & 15;
    const int k0 = kq * 4;

    ull acc[4][4];                    // [pair][col], halves = (row 2p, row 2p+1)

    // ================= stage 1: enc1 = relu(S @ W1 + b1) =================
    #pragma unroll
    for (int p = 0; p < 4; ++p)
        #pragma unroll
        for (int c = 0; c < 4; ++c) acc[p][c] = 0ull;

    #pragma unroll 1
    for (int ch = 0; ch < 4; ++ch) {
        __syncthreads();
        // load S chunk [32 rows x 128 k] into pair-transposed sS
        {
            const float* rA = S + (size_t)(row0 + 2 * pr) * 512 + ch * 128 + k0;
            const float* rB = rA + 512;
            const float4 a0 = *(const float4*)rA;
            const float4 a1 = *(const float4*)(rA + 64);
            const float4 b0 = *(const float4*)rB;
            const float4 b1v = *(const float4*)(rB + 64);
            sS[k0 + 0][pr]      = make_float2(a0.x, b0.x);
            sS[k0 + 1][pr]      = make_float2(a0.y, b0.y);
            sS[k0 + 2][pr]      = make_float2(a0.z, b0.z);
            sS[k0 + 3][pr]      = make_float2(a0.w, b0.w);
            sS[k0 + 64 + 0][pr] = make_float2(a1.x, b1v.x);
            sS[k0 + 64 + 1][pr] = make_float2(a1.y, b1v.y);
            sS[k0 + 64 + 2][pr] = make_float2(a1.z, b1v.z);
            sS[k0 + 64 + 3][pr] = make_float2(a1.w, b1v.w);
        }
        __syncthreads();

        const float* Wp = W1 + (size_t)(ch * 128) * 256;
        #pragma unroll 4
        for (int k = 0; k < 128; ++k) {
            const float4 wv = *(const float4*)(Wp + k * 256 + c0);   // LDG.128, 4 wf
            const ull wd0 = packf2(wv.x, wv.x);
            const ull wd1 = packf2(wv.y, wv.y);
            const ull wd2 = packf2(wv.z, wv.z);
            const ull wd3 = packf2(wv.w, wv.w);
            const ulonglong2 sA = *(const ulonglong2*)&sS[k][p0];     // pairs p0,p0+1 (bcast)
            const ulonglong2 sB = *(const ulonglong2*)&sS[k][p0 + 2]; // pairs p0+2,p0+3
            ffma2(acc[0][0], sA.x, wd0); ffma2(acc[0][1], sA.x, wd1);
            ffma2(acc[0][2], sA.x, wd2); ffma2(acc[0][3], sA.x, wd3);
            ffma2(acc[1][0], sA.y, wd0); ffma2(acc[1][1], sA.y, wd1);
            ffma2(acc[1][2], sA.y, wd2); ffma2(acc[1][3], sA.y, wd3);
            ffma2(acc[2][0], sB.x, wd0); ffma2(acc[2][1], sB.x, wd1);
            ffma2(acc[2][2], sB.x, wd2); ffma2(acc[2][3], sB.x, wd3);
            ffma2(acc[3][0], sB.y, wd0); ffma2(acc[3][1], sB.y, wd1);
            ffma2(acc[3][2], sB.y, wd2); ffma2(acc[3][3], sB.y, wd3);
        }
    }
    __syncthreads();   // sS fully consumed

    // epilogue 1: bias + relu -> sE1[col][pair]  (pair-transposed for stage 2)
    {
        const float4 bb = *(const float4*)(b1 + c0);
        const float bc[4] = {bb.x, bb.y, bb.z, bb.w};
        #pragma unroll
        for (int c = 0; c < 4; ++c)
            #pragma unroll
            for (int p = 0; p < 4; ++p) {
                float2 v = unpackf2(acc[p][c]);
                sE1[c0 + c][p0 + p] =
                    make_float2(fmaxf(v.x + bc[c], 0.f), fmaxf(v.y + bc[c], 0.f));
            }
    }
    __syncthreads();

    // ================= stage 2: enc2 = relu(enc1 @ W2 + b2) =================
    #pragma unroll
    for (int p = 0; p < 4; ++p)
        #pragma unroll
        for (int c = 0; c < 4; ++c) acc[p][c] = 0ull;

    #pragma unroll 4
    for (int k = 0; k < 256; ++k) {
        const float4 wv = *(const float4*)(W2 + k * 256 + c0);
        const ull wd0 = packf2(wv.x, wv.x);
        const ull wd1 = packf2(wv.y, wv.y);
        const ull wd2 = packf2(wv.z, wv.z);
        const ull wd3 = packf2(wv.w, wv.w);
        const ulonglong2 sA = *(const ulonglong2*)&sE1[k][p0];
        const ulonglong2 sB = *(const ulonglong2*)&sE1[k][p0 + 2];
        ffma2(acc[0][0], sA.x, wd0); ffma2(acc[0][1], sA.x, wd1);
        ffma2(acc[0][2], sA.x, wd2); ffma2(acc[0][3], sA.x, wd3);
        ffma2(acc[1][0], sA.y, wd0); ffma2(acc[1][1], sA.y, wd1);
        ffma2(acc[1][2], sA.y, wd2); ffma2(acc[1][3], sA.y, wd3);
        ffma2(acc[2][0], sB.x, wd0); ffma2(acc[2][1], sB.x, wd1);
        ffma2(acc[2][2], sB.x, wd2); ffma2(acc[2][3], sB.x, wd3);
        ffma2(acc[3][0], sB.y, wd0); ffma2(acc[3][1], sB.y, wd1);
        ffma2(acc[3][2], sB.y, wd2); ffma2(acc[3][3], sB.y, wd3);
    }

    // epilogue 2: bias + relu -> sE2[col][pair]  (overlays dead sS)
    {
        const float4 bb = *(const float4*)(b2 + c0);
        const float bc[4] = {bb.x, bb.y, bb.z, bb.w};
        #pragma unroll
        for (int c = 0; c < 4; ++c)
            #pragma unroll
            for (int p = 0; p < 4; ++p) {
                float2 v = unpackf2(acc[p][c]);
                sE2[c0 + c][p0 + p] =
                    make_float2(fmaxf(v.x + bc[c], 0.f), fmaxf(v.y + bc[c], 0.f));
            }
    }
    __syncthreads();

    // ========= stage 3: q = tanh(enc2 @ Wq + bq);  p = q . Wh =========
    float part;
    {
        const int rg3 = tid >> 4;     // pair 0..15 (rows 2rg3, 2rg3+1)
        const int cg3 = tid & 15;     // cols cg3*4 .. +3
        const int c3  = cg3 * 4;

        ull a3[4] = {0ull, 0ull, 0ull, 0ull};
        #pragma unroll 4
        for (int k = 0; k < 256; ++k) {
            const float4 wv = *(const float4*)(Wq + k * 64 + c3);
            const ull sp = *(const ull*)&sE2[k][rg3];    // LDS.64 broadcast
            ffma2(a3[0], sp, packf2(wv.x, wv.x));
            ffma2(a3[1], sp, packf2(wv.y, wv.y));
            ffma2(a3[2], sp, packf2(wv.z, wv.z));
            ffma2(a3[3], sp, packf2(wv.w, wv.w));
        }
        const float4 bqv = *(const float4*)(bq + c3);
        const float4 whv = *(const float4*)(Wh + c3);
        const float bqa[4] = {bqv.x, bqv.y, bqv.z, bqv.w};
        const float wha[4] = {whv.x, whv.y, whv.z, whv.w};
        part = 0.f;
        #pragma unroll
        for (int c = 0; c < 4; ++c) {
            float2 v = unpackf2(a3[c]);
            part += (tanhf(v.x + bqa[c]) + tanhf(v.y + bqa[c])) * wha[c];
        }
    }

    // ---- block reduce (fixed order) ----
    #pragma unroll
    for (int o = 16; o > 0; o >>= 1)
        part += __shfl_down_sync(0xffffffffu, part, o);
    if (lane == 0) sRed[w] = part;
    __syncthreads();

    if (tid == 0) {
        float tot = 0.f;
        #pragma unroll
        for (int i = 0; i < 8; ++i) tot += sRed[i];
        g_partials[blockIdx.x] = tot;
        __threadfence();
        unsigned int c = atomicAdd(&g_count, 1u);
        sIsLast = (c == NBLK - 1u);
    }
    __syncthreads();

    // ---- last-done block: deterministic final reduction ----
    if (sIsLast) {
        volatile float* gp = g_partials;
        float v = gp[tid];                       // NBLK == NTHREADS == 256
        #pragma unroll
        for (int o = 16; o > 0; o >>= 1)
            v += __shfl_down_sync(0xffffffffu, v, o);
        if (lane == 0) sRed[w] = v;
        __syncthreads();
        if (tid == 0) {
            float t = 0.f;
            #pragma unroll
            for (int i = 0; i < 8; ++i) t += sRed[i];
            out[0] = t + bh[0];
            g_count = 0;                          // self-reset for graph replay
        }
    }
}

extern "C" void kernel_launch(void* const* d_in, const int* in_sizes, int n_in,
                              void* d_out, int out_size)
{
    const float* S  = (const float*)d_in[0];
    const float* W1 = (const float*)d_in[1];
    const float* b1 = (const float*)d_in[2];
    const float* W2 = (const float*)d_in[3];
    const float* b2 = (const float*)d_in[4];
    const float* Wq = (const float*)d_in[5];
    const float* bq = (const float*)d_in[6];
    const float* Wh = (const float*)d_in[7];
    const float* bh = (const float*)d_in[8];
    float* out = (float*)d_out;

    const int dynsm = 2 * 256 * PITCH * (int)sizeof(float2);   // 73728 B
    static int attr_set = 0;
    if (!attr_set) {
        cudaFuncSetAttribute(fused_mlp_kernel,
                             cudaFuncAttributeMaxDynamicSharedMemorySize, dynsm);
        attr_set = 1;
    }
    fused_mlp_kernel<<<NBLK, NTHREADS, dynsm>>>(S, W1, b1, W2, b2, Wq, bq, Wh, bh, out);
}